// round 13
// baseline (speedup 1.0000x reference)
#include <cuda_runtime.h>
#include <cuda_fp16.h>

// BilateralGrid apply. Grid (16,16,8,12) f32 -> z-pair replicated fp16 smem:
// for each zp in [0,7), (y,x): a 48B block of 12 half2 = {coef_j@z=zp, coef_j@z=zp+1}.
// Each (y,x) corner = 3 aligned LDS.128; HFMA2 accumulation over the 4 corners;
// final z-lerp in fp32. This round: 512 threads x 2 CTAs/SM (32 warps, 50% occ),
// forced 64 regs, eager output stores to shorten register liveness.

#define SH 16
#define SW 16
#define SL 8
#define NTHREADS  512
#define NBLOCKS   304
#define NPAIRS    7                       // z0 in 0..6
#define SMEM_U32  (NPAIRS * 256 * 12)     // 21504 half2 words
#define SMEM_BYTES (SMEM_U32 * 4)         // 86016 bytes

__global__ __launch_bounds__(NTHREADS, 2)
void bilateral_grid_kernel(const float4* __restrict__ px4,
                           const float4* __restrict__ co4,
                           const float* __restrict__ gridf,
                           float4* __restrict__ out4,
                           int nquad)
{
    extern __shared__ unsigned sgrid[];   // half2 per word; 16B-aligned base

    // ---- one-time fill: replicate grid into z-pair interleaved fp16 blocks ----
    // dst word index = blk*12 + j, blk = zp*256 + (y*16+x)
    // src: grid[(y*16+x)*8*12 + z*12 + j]
    #pragma unroll 4
    for (int idx = threadIdx.x; idx < SMEM_U32; idx += NTHREADS) {
        const int j   = idx % 12;
        const int blk = idx / 12;
        const int zp  = blk >> 8;
        const int yx  = blk & 255;
        const float a = gridf[(yx * SL + zp) * 12 + j];
        const float b = gridf[(yx * SL + zp + 1) * 12 + j];
        const __half2 h = __floats2half2_rn(a, b);
        sgrid[idx] = *reinterpret_cast<const unsigned*>(&h);
    }
    __syncthreads();

    const uint4* sg4 = reinterpret_cast<const uint4*>(sgrid);

    const int stride = gridDim.x * blockDim.x;
    for (int q = blockIdx.x * blockDim.x + threadIdx.x; q < nquad; q += stride) {
        // ---- coalesced streaming loads: 4 pixels (12 floats) + 4 coords (8 floats) ----
        const float4 pa = px4[3 * q + 0];
        const float4 pb = px4[3 * q + 1];
        const float4 pc = px4[3 * q + 2];
        const float4 ca = co4[2 * q + 0];
        const float4 cb = co4[2 * q + 1];

        const float pr[4]  = {pa.x, pa.w, pb.z, pc.y};
        const float pg[4]  = {pa.y, pb.x, pb.w, pc.z};
        const float pbv[4] = {pa.z, pb.y, pc.x, pc.w};
        const float cx[4]  = {ca.x, ca.z, cb.x, cb.z};
        const float cy[4]  = {ca.y, ca.w, cb.y, cb.w};

        float o[12];

        #pragma unroll
        for (int k = 0; k < 4; k++) {
            const float r = pr[k], g = pg[k], b = pbv[k];

            const float guide = 0.2126f * r + 0.7152f * g + 0.0722f * b;

            const float gx  = fminf(fmaxf(cx[k] * (float)(SW - 1), 0.0f), (float)SW - 1.001f);
            const float gy  = fminf(fmaxf(cy[k] * (float)(SH - 1), 0.0f), (float)SH - 1.001f);
            const float gcl = fminf(fmaxf(guide, 0.0f), 1.0f);
            const float gz  = fminf(fmaxf(gcl * (float)(SL - 1), 0.0f), (float)SL - 1.001f);

            const int x0 = (int)gx;
            const int y0 = (int)gy;
            const int z0 = (int)gz;
            const float fx = gx - (float)x0;
            const float fy = gy - (float)y0;
            const float fz = gz - (float)z0;

            const float wx0 = 1.0f - fx, wx1 = fx;
            const float wy0 = 1.0f - fy, wy1 = fy;

            // 4 (y,x) corner weights as broadcast half2; z handled at the end
            const __half2 wc[4] = {__float2half2_rn(wy0 * wx0),
                                   __float2half2_rn(wy0 * wx1),
                                   __float2half2_rn(wy1 * wx0),
                                   __float2half2_rn(wy1 * wx1)};

            // block index: zp*256 + y*16 + x ; uint4 index = blk*3
            const int base = (z0 << 8) + (y0 << 4) + x0;
            const int coff[4] = {0, 1, SW, SW + 1};

            __half2 acc[12];
            #pragma unroll
            for (int j = 0; j < 12; j++) acc[j] = __float2half2_rn(0.0f);

            #pragma unroll
            for (int c = 0; c < 4; c++) {
                const int bi = 3 * (base + coff[c]);
                const __half2 w2 = wc[c];
                const uint4 u0 = sg4[bi + 0];   // coefs 0..3  (half2: lo=z0, hi=z1)
                const uint4 u1 = sg4[bi + 1];   // coefs 4..7
                const uint4 u2 = sg4[bi + 2];   // coefs 8..11

                acc[0]  = __hfma2(w2, *reinterpret_cast<const __half2*>(&u0.x), acc[0]);
                acc[1]  = __hfma2(w2, *reinterpret_cast<const __half2*>(&u0.y), acc[1]);
                acc[2]  = __hfma2(w2, *reinterpret_cast<const __half2*>(&u0.z), acc[2]);
                acc[3]  = __hfma2(w2, *reinterpret_cast<const __half2*>(&u0.w), acc[3]);
                acc[4]  = __hfma2(w2, *reinterpret_cast<const __half2*>(&u1.x), acc[4]);
                acc[5]  = __hfma2(w2, *reinterpret_cast<const __half2*>(&u1.y), acc[5]);
                acc[6]  = __hfma2(w2, *reinterpret_cast<const __half2*>(&u1.z), acc[6]);
                acc[7]  = __hfma2(w2, *reinterpret_cast<const __half2*>(&u1.w), acc[7]);
                acc[8]  = __hfma2(w2, *reinterpret_cast<const __half2*>(&u2.x), acc[8]);
                acc[9]  = __hfma2(w2, *reinterpret_cast<const __half2*>(&u2.y), acc[9]);
                acc[10] = __hfma2(w2, *reinterpret_cast<const __half2*>(&u2.z), acc[10]);
                acc[11] = __hfma2(w2, *reinterpret_cast<const __half2*>(&u2.w), acc[11]);
            }

            // final fp32 z-lerp per coefficient
            float A[12];
            #pragma unroll
            for (int j = 0; j < 12; j++) {
                const float2 f = __half22float2(acc[j]);
                A[j] = fmaf(fz, f.y - f.x, f.x);
            }

            // affine rows: (A[0..3]), (A[4..7]), (A[8..11])
            o[3 * k + 0] = fmaf(A[0], r, fmaf(A[1],  g, fmaf(A[2],  b, A[3])));
            o[3 * k + 1] = fmaf(A[4], r, fmaf(A[5],  g, fmaf(A[6],  b, A[7])));
            o[3 * k + 2] = fmaf(A[8], r, fmaf(A[9],  g, fmaf(A[10], b, A[11])));

            // eager drains: shorten o[] liveness so 64 regs fit without spills
            if (k == 1) out4[3 * q + 0] = make_float4(o[0], o[1], o[2], o[3]);
            if (k == 2) out4[3 * q + 1] = make_float4(o[4], o[5], o[6], o[7]);
            if (k == 3) out4[3 * q + 2] = make_float4(o[8], o[9], o[10], o[11]);
        }
    }
}

extern "C" void kernel_launch(void* const* d_in, const int* in_sizes, int n_in,
                              void* d_out, int out_size)
{
    const float4* px4 = (const float4*)d_in[0];   // pixels (B,H,W,3) f32
    const float4* co4 = (const float4*)d_in[1];   // coords (B,H,W,2) f32
    const float*  grf = (const float*)d_in[2];    // grid (16,16,8,12) f32
    float4* out4 = (float4*)d_out;

    const int N = in_sizes[0] / 3;   // number of pixels
    const int nquad = N / 4;         // 8294400 / 4

    cudaFuncSetAttribute(bilateral_grid_kernel,
                         cudaFuncAttributeMaxDynamicSharedMemorySize, SMEM_BYTES);

    bilateral_grid_kernel<<<NBLOCKS, NTHREADS, SMEM_BYTES>>>(px4, co4, grf, out4, nquad);
}

// round 16
// speedup vs baseline: 1.0136x; 1.0136x over previous
#include <cuda_runtime.h>
#include <cuda_fp16.h>

// BilateralGrid apply. Grid (16,16,8,12) f32 -> z-pair replicated fp16 smem:
// for each zp in [0,7), (y,x): a 48B block of 12 half2 = {coef_j@z=zp, coef_j@z=zp+1}.
// Each (y,x) corner = 3 aligned LDS.128; HFMA2 accumulation; final z-lerp fp32.
// This round: 384thr x 2 CTAs (best-known), gathers interleaved in PIXEL PAIRS:
// both pixels' indices computed first, then 6 independent LDS.128 per corner step
// -> 2x per-thread LDS MLP to cover the ~29cyc LDS latency + replay pipeline.

#define SH 16
#define SW 16
#define SL 8
#define NTHREADS  384
#define NBLOCKS   304
#define NPAIRS    7                       // z0 in 0..6
#define SMEM_U32  (NPAIRS * 256 * 12)     // 21504 half2 words
#define SMEM_BYTES (SMEM_U32 * 4)         // 86016 bytes

struct PixPrep {
    int    base;     // block index (z0<<8 | y0<<4 | x0)
    float  fz;
    __half2 wc[4];   // (y,x) corner weights, broadcast half2
};

__device__ __forceinline__ PixPrep prep_pixel(float r, float g, float b,
                                              float cxv, float cyv)
{
    PixPrep pp;
    const float guide = 0.2126f * r + 0.7152f * g + 0.0722f * b;

    const float gx  = fminf(fmaxf(cxv * (float)(SW - 1), 0.0f), (float)SW - 1.001f);
    const float gy  = fminf(fmaxf(cyv * (float)(SH - 1), 0.0f), (float)SH - 1.001f);
    const float gcl = fminf(fmaxf(guide, 0.0f), 1.0f);
    const float gz  = fminf(fmaxf(gcl * (float)(SL - 1), 0.0f), (float)SL - 1.001f);

    const int x0 = (int)gx;
    const int y0 = (int)gy;
    const int z0 = (int)gz;
    const float fx = gx - (float)x0;
    const float fy = gy - (float)y0;
    pp.fz = gz - (float)z0;

    const float wx0 = 1.0f - fx, wx1 = fx;
    const float wy0 = 1.0f - fy, wy1 = fy;
    pp.wc[0] = __float2half2_rn(wy0 * wx0);
    pp.wc[1] = __float2half2_rn(wy0 * wx1);
    pp.wc[2] = __float2half2_rn(wy1 * wx0);
    pp.wc[3] = __float2half2_rn(wy1 * wx1);

    pp.base = (z0 << 8) + (y0 << 4) + x0;
    return pp;
}

// Interleaved dual-pixel gather: 8 corner-block loads (6 LDS.128-equiv per step
// pairwise independent), HFMA2 accumulation into accA/accB.
__device__ __forceinline__ void gather_pair(const uint4* __restrict__ sg4,
                                            const PixPrep& A, const PixPrep& B,
                                            __half2* __restrict__ accA,
                                            __half2* __restrict__ accB)
{
    const int coff[4] = {0, 1, SW, SW + 1};
    #pragma unroll
    for (int c = 0; c < 4; c++) {
        const int biA = 3 * (A.base + coff[c]);
        const int biB = 3 * (B.base + coff[c]);
        const uint4 a0 = sg4[biA + 0];
        const uint4 b0 = sg4[biB + 0];
        const uint4 a1 = sg4[biA + 1];
        const uint4 b1 = sg4[biB + 1];
        const uint4 a2 = sg4[biA + 2];
        const uint4 b2 = sg4[biB + 2];
        const __half2 wA = A.wc[c];
        const __half2 wB = B.wc[c];

        const unsigned ua[12] = {a0.x, a0.y, a0.z, a0.w, a1.x, a1.y,
                                 a1.z, a1.w, a2.x, a2.y, a2.z, a2.w};
        const unsigned ub[12] = {b0.x, b0.y, b0.z, b0.w, b1.x, b1.y,
                                 b1.z, b1.w, b2.x, b2.y, b2.z, b2.w};
        #pragma unroll
        for (int j = 0; j < 12; j++) {
            accA[j] = __hfma2(wA, *reinterpret_cast<const __half2*>(&ua[j]), accA[j]);
            accB[j] = __hfma2(wB, *reinterpret_cast<const __half2*>(&ub[j]), accB[j]);
        }
    }
}

__device__ __forceinline__ void finish_pixel(const __half2* __restrict__ acc,
                                             float fz, float r, float g, float b,
                                             float* __restrict__ o)  // o[3]
{
    float A[12];
    #pragma unroll
    for (int j = 0; j < 12; j++) {
        const float2 f = __half22float2(acc[j]);
        A[j] = fmaf(fz, f.y - f.x, f.x);
    }
    o[0] = fmaf(A[0], r, fmaf(A[1],  g, fmaf(A[2],  b, A[3])));
    o[1] = fmaf(A[4], r, fmaf(A[5],  g, fmaf(A[6],  b, A[7])));
    o[2] = fmaf(A[8], r, fmaf(A[9],  g, fmaf(A[10], b, A[11])));
}

__global__ __launch_bounds__(NTHREADS, 2)
void bilateral_grid_kernel(const float4* __restrict__ px4,
                           const float4* __restrict__ co4,
                           const float* __restrict__ gridf,
                           float4* __restrict__ out4,
                           int nquad)
{
    extern __shared__ unsigned sgrid[];   // half2 per word; 16B-aligned base

    // ---- one-time fill: replicate grid into z-pair interleaved fp16 blocks ----
    #pragma unroll 4
    for (int idx = threadIdx.x; idx < SMEM_U32; idx += NTHREADS) {
        const int j   = idx % 12;
        const int blk = idx / 12;
        const int zp  = blk >> 8;
        const int yx  = blk & 255;
        const float a = gridf[(yx * SL + zp) * 12 + j];
        const float b = gridf[(yx * SL + zp + 1) * 12 + j];
        const __half2 h = __floats2half2_rn(a, b);
        sgrid[idx] = *reinterpret_cast<const unsigned*>(&h);
    }
    __syncthreads();

    const uint4* sg4 = reinterpret_cast<const uint4*>(sgrid);

    const int stride = gridDim.x * blockDim.x;
    for (int q = blockIdx.x * blockDim.x + threadIdx.x; q < nquad; q += stride) {
        // ---- coalesced streaming loads: 4 pixels (12 floats) + 4 coords (8 floats) ----
        const float4 pa = px4[3 * q + 0];
        const float4 pb = px4[3 * q + 1];
        const float4 pc = px4[3 * q + 2];
        const float4 ca = co4[2 * q + 0];
        const float4 cb = co4[2 * q + 1];

        const float pr[4]  = {pa.x, pa.w, pb.z, pc.y};
        const float pg[4]  = {pa.y, pb.x, pb.w, pc.z};
        const float pbv[4] = {pa.z, pb.y, pc.x, pc.w};
        const float cx[4]  = {ca.x, ca.z, cb.x, cb.z};
        const float cy[4]  = {ca.y, ca.w, cb.y, cb.w};

        float o[12];

        // ---- pair 0: pixels 0 & 1 ----
        {
            const PixPrep p0 = prep_pixel(pr[0], pg[0], pbv[0], cx[0], cy[0]);
            const PixPrep p1 = prep_pixel(pr[1], pg[1], pbv[1], cx[1], cy[1]);
            __half2 accA[12], accB[12];
            #pragma unroll
            for (int j = 0; j < 12; j++) { accA[j] = __float2half2_rn(0.0f);
                                           accB[j] = __float2half2_rn(0.0f); }
            gather_pair(sg4, p0, p1, accA, accB);
            finish_pixel(accA, p0.fz, pr[0], pg[0], pbv[0], &o[0]);
            finish_pixel(accB, p1.fz, pr[1], pg[1], pbv[1], &o[3]);
        }

        // ---- pair 1: pixels 2 & 3 ----
        {
            const PixPrep p2 = prep_pixel(pr[2], pg[2], pbv[2], cx[2], cy[2]);
            const PixPrep p3 = prep_pixel(pr[3], pg[3], pbv[3], cx[3], cy[3]);
            __half2 accA[12], accB[12];
            #pragma unroll
            for (int j = 0; j < 12; j++) { accA[j] = __float2half2_rn(0.0f);
                                           accB[j] = __float2half2_rn(0.0f); }
            gather_pair(sg4, p2, p3, accA, accB);
            finish_pixel(accA, p2.fz, pr[2], pg[2], pbv[2], &o[6]);
            finish_pixel(accB, p3.fz, pr[3], pg[3], pbv[3], &o[9]);
        }

        // ---- coalesced streaming stores: 12 floats -> 3 float4 ----
        out4[3 * q + 0] = make_float4(o[0], o[1], o[2],  o[3]);
        out4[3 * q + 1] = make_float4(o[4], o[5], o[6],  o[7]);
        out4[3 * q + 2] = make_float4(o[8], o[9], o[10], o[11]);
    }
}

extern "C" void kernel_launch(void* const* d_in, const int* in_sizes, int n_in,
                              void* d_out, int out_size)
{
    const float4* px4 = (const float4*)d_in[0];   // pixels (B,H,W,3) f32
    const float4* co4 = (const float4*)d_in[1];   // coords (B,H,W,2) f32
    const float*  grf = (const float*)d_in[2];    // grid (16,16,8,12) f32
    float4* out4 = (float4*)d_out;

    const int N = in_sizes[0] / 3;   // number of pixels
    const int nquad = N / 4;         // 8294400 / 4

    cudaFuncSetAttribute(bilateral_grid_kernel,
                         cudaFuncAttributeMaxDynamicSharedMemorySize, SMEM_BYTES);

    bilateral_grid_kernel<<<NBLOCKS, NTHREADS, SMEM_BYTES>>>(px4, co4, grf, out4, nquad);
}